// round 10
// baseline (speedup 1.0000x reference)
#include <cuda_runtime.h>
#include <math.h>

#define NUSERS 100000
#define NITEMS 50000
#define NFEATS 512
#define DIM 32
#define ESOC 3200000
#define EUI 3200000
#define NPAIRS 1000000
#define SCAN_T 1024
#define CHUNK 98            // ceil(NUSERS / SCAN_T)

// ---------------- scratch (device globals; no allocs allowed) ----------------
__device__ double g_red[8];
__device__ float  g_colsum[DIM];
__device__ float  g_user_sig[NUSERS * DIM];
__device__ float  g_item_sig[NITEMS * DIM];
__device__ float  g_user_fus[NUSERS * DIM];
__device__ float  g_item_fus[NITEMS * DIM];
__device__ float  g_h1[NUSERS * DIM];
__device__ float  g_last[NUSERS * DIM];
// CSR scratch
__device__ int    g_cntU[NUSERS],  g_cntS[NUSERS];
__device__ int    g_startU[NUSERS], g_startS[NUSERS];
__device__ int    g_curU[NUSERS],  g_curS[NUSERS];
__device__ int    g_part[SCAN_T];
__device__ float2 g_ui_cv[EUI];     // (col bitcast, val) packed
__device__ float2 g_soc_cv[ESOC];

// ---------------- zero counters ----------------
__global__ void k_zero() {
    int i = blockIdx.x * blockDim.x + threadIdx.x;
    if (i < NUSERS) {
        g_cntU[i] = 0; g_cntS[i] = 0;
        g_curU[i] = 0; g_curS[i] = 0;
    }
    if (i < 8) g_red[i] = 0.0;
}

// ---------------- column sums of W ----------------
__global__ void k_colsum(const float* __restrict__ W) {
    __shared__ float s[8][DIM];
    int c = threadIdx.x & 31;
    int g = threadIdx.x >> 5;
    float acc = 0.f;
    for (int k = g; k < NFEATS; k += 8) acc += W[k * DIM + c];
    s[g][c] = acc;
    __syncthreads();
    if (g == 0) {
        float t = 0.f;
#pragma unroll
        for (int j = 0; j < 8; j++) t += s[j][c];
        g_colsum[c] = t;
    }
}

// ---------------- CSR build: histogram ----------------
__global__ void k_hist(const int* __restrict__ rows, int nE, int sel) {
    int* cnt = sel ? g_cntS : g_cntU;
    int i = blockIdx.x * blockDim.x + threadIdx.x;
    if (i < nE) atomicAdd(&cnt[rows[i]], 1);
}

// ---------------- CSR build: 3-step exclusive scan ----------------
__global__ void k_scan1(int sel) {
    const int* cnt = sel ? g_cntS : g_cntU;
    int t = threadIdx.x;
    int s = 0, base = t * CHUNK;
#pragma unroll 4
    for (int i = 0; i < CHUNK; ++i) {
        int r = base + i;
        if (r < NUSERS) s += cnt[r];
    }
    g_part[t] = s;
}
__global__ void k_scan2() {
    __shared__ int sm[SCAN_T];
    int t = threadIdx.x;
    int v = g_part[t];
    sm[t] = v;
    __syncthreads();
    for (int off = 1; off < SCAN_T; off <<= 1) {
        int y = (t >= off) ? sm[t - off] : 0;
        __syncthreads();
        sm[t] += y;
        __syncthreads();
    }
    g_part[t] = sm[t] - v;   // exclusive
}
__global__ void k_scan3(int sel) {
    const int* cnt = sel ? g_cntS : g_cntU;
    int* start = sel ? g_startS : g_startU;
    int t = threadIdx.x;
    int base = g_part[t];
    int r0 = t * CHUNK;
    for (int i = 0; i < CHUNK; ++i) {
        int r = r0 + i;
        if (r < NUSERS) { start[r] = base; base += cnt[r]; }
    }
}

// ---------------- CSR build: scatter (col,val) pairs ----------------
__global__ void k_scatter(const int* __restrict__ rows, const int* __restrict__ cols,
                          const float* __restrict__ vals, int nE, int sel) {
    int* cur = sel ? g_curS : g_curU;
    const int* start = sel ? g_startS : g_startU;
    float2* cv = sel ? g_soc_cv : g_ui_cv;
    int i = blockIdx.x * blockDim.x + threadIdx.x;
    if (i < nE) {
        int r = rows[i];
        int pos = start[r] + atomicAdd(&cur[r], 1);
        cv[pos] = make_float2(__int_as_float(cols[i]), vals[i]);
    }
}

// ---------------- GEMM (proven): 64x32 tile, 4x4 per thread, fused stats ----------------
__global__ __launch_bounds__(128) void k_gemm(const float* __restrict__ F,
                                              const float* __restrict__ W,
                                              int M, int redIdx, int outSel) {
    __shared__ float sF[64][33];
    __shared__ float sW[32][36];
    float* __restrict__ out = outSel ? g_item_sig : g_user_sig;

    int t  = threadIdx.x;
    int tc = t & 7;
    int tr = t >> 3;
    int row0 = blockIdx.x * 64;

    float acc[4][4] = {};
    float lsum = 0.f, lsq = 0.f;

    for (int kt = 0; kt < NFEATS / 32; ++kt) {
        int k0 = kt * 32;
#pragma unroll
        for (int i = 0; i < 4; ++i) {
            int fi = t + i * 128;
            int r = fi >> 3, kq = fi & 7;
            float4 v = make_float4(0.f, 0.f, 0.f, 0.f);
            int grow = row0 + r;
            if (grow < M)
                v = *reinterpret_cast<const float4*>(&F[(size_t)grow * NFEATS + k0 + kq * 4]);
            sF[r][kq * 4 + 0] = v.x; sF[r][kq * 4 + 1] = v.y;
            sF[r][kq * 4 + 2] = v.z; sF[r][kq * 4 + 3] = v.w;
            lsum += v.x + v.y + v.z + v.w;
            lsq  += v.x * v.x + v.y * v.y + v.z * v.z + v.w * v.w;
        }
#pragma unroll
        for (int i = 0; i < 2; ++i) {
            int fi = t + i * 128;
            int kr = fi >> 3, kq = fi & 7;
            float4 w = *reinterpret_cast<const float4*>(&W[(size_t)(k0 + kr) * DIM + kq * 4]);
            sW[kr][kq * 4 + 0] = w.x; sW[kr][kq * 4 + 1] = w.y;
            sW[kr][kq * 4 + 2] = w.z; sW[kr][kq * 4 + 3] = w.w;
        }
        __syncthreads();
#pragma unroll
        for (int k = 0; k < 32; ++k) {
            float4 w = *reinterpret_cast<float4*>(&sW[k][tc * 4]);
            float f0 = sF[tr * 4 + 0][k];
            float f1 = sF[tr * 4 + 1][k];
            float f2 = sF[tr * 4 + 2][k];
            float f3 = sF[tr * 4 + 3][k];
            acc[0][0] += f0 * w.x; acc[0][1] += f0 * w.y; acc[0][2] += f0 * w.z; acc[0][3] += f0 * w.w;
            acc[1][0] += f1 * w.x; acc[1][1] += f1 * w.y; acc[1][2] += f1 * w.z; acc[1][3] += f1 * w.w;
            acc[2][0] += f2 * w.x; acc[2][1] += f2 * w.y; acc[2][2] += f2 * w.z; acc[2][3] += f2 * w.w;
            acc[3][0] += f3 * w.x; acc[3][1] += f3 * w.y; acc[3][2] += f3 * w.z; acc[3][3] += f3 * w.w;
        }
        __syncthreads();
    }

#pragma unroll
    for (int o = 16; o; o >>= 1) {
        lsum += __shfl_down_sync(0xffffffffu, lsum, o);
        lsq  += __shfl_down_sync(0xffffffffu, lsq, o);
    }
    __shared__ double sred[4][2];
    int wid = t >> 5, lane = t & 31;
    if (lane == 0) { sred[wid][0] = (double)lsum; sred[wid][1] = (double)lsq; }
    __syncthreads();
    if (t == 0) {
        double a = 0.0, b = 0.0;
#pragma unroll
        for (int j = 0; j < 4; j++) { a += sred[j][0]; b += sred[j][1]; }
        atomicAdd(&g_red[redIdx], a);
        atomicAdd(&g_red[redIdx + 1], b);
    }

#pragma unroll
    for (int i = 0; i < 4; ++i) {
        int grow = row0 + tr * 4 + i;
        if (grow < M) {
            float4 o4 = make_float4(acc[i][0], acc[i][1], acc[i][2], acc[i][3]);
            *reinterpret_cast<float4*>(&out[(size_t)grow * DIM + tc * 4]) = o4;
        }
    }
}

// ---------------- epilogue: fold feature-norm + sigmoid + sig-stats ----------------
__global__ void k_epi(const float* __restrict__ b, int n, double Nfeat,
                      int si, int so, int sel) {
    float* __restrict__ sig = sel ? g_item_sig : g_user_sig;
    double fsum = g_red[si], fsq = g_red[si + 1];
    double mean = fsum / Nfeat;
    double var  = (fsq - fsum * fsum / Nfeat) / (Nfeat - 1.0);
    float inv_s = (float)(1.0 / sqrt(var));
    float mis   = (float)mean * inv_s;

    int i = blockIdx.x * blockDim.x + threadIdx.x;
    double lsum = 0.0, lsq = 0.0;
    if (i < n) {
        int j = i & (DIM - 1);
        float x = sig[i] * inv_s + b[j] - mis * g_colsum[j];
        float v = 1.f / (1.f + expf(-x));
        sig[i] = v;
        lsum = v;
        lsq  = (double)v * v;
    }
#pragma unroll
    for (int o = 16; o; o >>= 1) {
        lsum += __shfl_down_sync(0xffffffffu, lsum, o);
        lsq  += __shfl_down_sync(0xffffffffu, lsq, o);
    }
    __shared__ double sred[8][2];
    int wid = threadIdx.x >> 5, lane = threadIdx.x & 31;
    if (lane == 0) { sred[wid][0] = lsum; sred[wid][1] = lsq; }
    __syncthreads();
    if (threadIdx.x == 0) {
        double a = 0.0, c = 0.0;
#pragma unroll
        for (int j = 0; j < 8; j++) { a += sred[j][0]; c += sred[j][1]; }
        atomicAdd(&g_red[so], a);
        atomicAdd(&g_red[so + 1], c);
    }
}

// ---------------- fusion ----------------
__global__ void k_fusion(const float* __restrict__ emb, int n, int si, int sel) {
    const float* __restrict__ sig = sel ? g_item_sig : g_user_sig;
    float* __restrict__ fus = sel ? g_item_fus : g_user_fus;
    double s0 = g_red[si], s1 = g_red[si + 1];
    double N = (double)n;
    double mean = s0 / N;
    double var  = (s1 - s0 * s0 / N) / (N - 1.0);
    float inv = (float)(1.0 / sqrt(var));
    float m   = (float)mean;
    int i = blockIdx.x * blockDim.x + threadIdx.x;
    if (i < n) fus[i] = (sig[i] - m) * inv + emb[i];
}

// ---------------- CSR SpMM: 8 lanes/row, register accumulation, NO atomics ----------------
__global__ __launch_bounds__(256) void k_spmm_csr(int selG, int selX, int accum) {
    const int* start = selG ? g_startS : g_startU;
    const int* cnt   = selG ? g_cntS   : g_cntU;
    const float2* __restrict__ cv = selG ? g_soc_cv : g_ui_cv;
    const float* __restrict__ X =
        (selX == 0) ? g_item_fus : (selX == 1) ? g_user_fus : g_h1;
    float* __restrict__ OUT = (selX == 1) ? g_h1 : g_last;

    int tid = blockIdx.x * blockDim.x + threadIdx.x;
    int row = tid >> 3;
    int sub = tid & 7;
    if (row >= NUSERS) return;

    int st = start[row];
    int n  = cnt[row];

    float4 a0 = make_float4(0.f, 0.f, 0.f, 0.f);
    float4 a1 = a0, a2 = a0, a3 = a0;

    int e = 0;
    for (; e + 4 <= n; e += 4) {
        float2 p0 = cv[st + e + 0];
        float2 p1 = cv[st + e + 1];
        float2 p2 = cv[st + e + 2];
        float2 p3 = cv[st + e + 3];
        float4 x0 = *reinterpret_cast<const float4*>(&X[(size_t)__float_as_int(p0.x) * DIM + sub * 4]);
        float4 x1 = *reinterpret_cast<const float4*>(&X[(size_t)__float_as_int(p1.x) * DIM + sub * 4]);
        float4 x2 = *reinterpret_cast<const float4*>(&X[(size_t)__float_as_int(p2.x) * DIM + sub * 4]);
        float4 x3 = *reinterpret_cast<const float4*>(&X[(size_t)__float_as_int(p3.x) * DIM + sub * 4]);
        a0.x += p0.y * x0.x; a0.y += p0.y * x0.y; a0.z += p0.y * x0.z; a0.w += p0.y * x0.w;
        a1.x += p1.y * x1.x; a1.y += p1.y * x1.y; a1.z += p1.y * x1.z; a1.w += p1.y * x1.w;
        a2.x += p2.y * x2.x; a2.y += p2.y * x2.y; a2.z += p2.y * x2.z; a2.w += p2.y * x2.w;
        a3.x += p3.y * x3.x; a3.y += p3.y * x3.y; a3.z += p3.y * x3.z; a3.w += p3.y * x3.w;
    }
    for (; e < n; ++e) {
        float2 p = cv[st + e];
        float4 x = *reinterpret_cast<const float4*>(&X[(size_t)__float_as_int(p.x) * DIM + sub * 4]);
        a0.x += p.y * x.x; a0.y += p.y * x.y; a0.z += p.y * x.z; a0.w += p.y * x.w;
    }
    float4 a = make_float4(a0.x + a1.x + a2.x + a3.x,
                           a0.y + a1.y + a2.y + a3.y,
                           a0.z + a1.z + a2.z + a3.z,
                           a0.w + a1.w + a2.w + a3.w);
    float* op = &OUT[(size_t)row * DIM + sub * 4];
    if (accum) {
        float4 o = *reinterpret_cast<float4*>(op);
        a.x += o.x; a.y += o.y; a.z += o.z; a.w += o.w;
    }
    *reinterpret_cast<float4*>(op) = a;
}

// ---------------- prediction: smem-staged indices ----------------
__global__ __launch_bounds__(256) void k_pred(const int* __restrict__ ui,
                                              const int* __restrict__ ii,
                                              float* __restrict__ out, int out_size) {
    __shared__ int su[256];
    __shared__ int sI[256];
    int base = blockIdx.x << 8;
    int t = threadIdx.x;
    int n = NPAIRS - base; if (n > 256) n = 256;
    if (t < n) { su[t] = ui[base + t]; sI[t] = ii[base + t]; }
    __syncthreads();

    int sub = t & 7, grp = t >> 3;
    for (int p = grp; p < n; p += 32) {
        int u  = su[p];
        int it = sI[p];
        float4 a = *reinterpret_cast<const float4*>(&g_last[(size_t)u * DIM + sub * 4]);
        float4 b = *reinterpret_cast<const float4*>(&g_item_fus[(size_t)it * DIM + sub * 4]);
        float d = a.x * b.x + a.y * b.y + a.z * b.z + a.w * b.w;
#pragma unroll
        for (int o = 4; o; o >>= 1) d += __shfl_down_sync(0xffffffffu, d, o, 8);
        if (sub == 0) {
            int gp = base + p;
            if (gp < out_size) out[gp] = d;
            if (NPAIRS + gp < out_size) out[NPAIRS + gp] = 1.f / (1.f + expf(-d));
        }
    }
}

// ---------------- launch ----------------
extern "C" void kernel_launch(void* const* d_in, const int* in_sizes, int n_in,
                              void* d_out, int out_size) {
    const float* uf    = (const float*)d_in[0];
    const float* itf   = (const float*)d_in[1];
    const float* uemb  = (const float*)d_in[2];
    const float* iemb  = (const float*)d_in[3];
    const float* wr_w  = (const float*)d_in[4];
    const float* wr_b  = (const float*)d_in[5];
    const int*   srows = (const int*)d_in[6];
    const int*   scols = (const int*)d_in[7];
    const float* svals = (const float*)d_in[8];
    const int*   urows = (const int*)d_in[9];
    const int*   ucols = (const int*)d_in[10];
    const float* uvals = (const float*)d_in[11];
    const int*   uidx  = (const int*)d_in[12];
    const int*   iidx  = (const int*)d_in[13];
    float* out = (float*)d_out;

    k_zero<<<(NUSERS + 255) / 256, 256>>>();
    k_colsum<<<1, 256>>>(wr_w);

    // CSR builds (UI then social)
    k_hist<<<(EUI + 255) / 256, 256>>>(urows, EUI, 0);
    k_hist<<<(ESOC + 255) / 256, 256>>>(srows, ESOC, 1);
    k_scan1<<<1, SCAN_T>>>(0);
    k_scan2<<<1, SCAN_T>>>();
    k_scan3<<<1, SCAN_T>>>(0);
    k_scan1<<<1, SCAN_T>>>(1);
    k_scan2<<<1, SCAN_T>>>();
    k_scan3<<<1, SCAN_T>>>(1);
    k_scatter<<<(EUI + 255) / 256, 256>>>(urows, ucols, uvals, EUI, 0);
    k_scatter<<<(ESOC + 255) / 256, 256>>>(srows, scols, svals, ESOC, 1);

    // dense pipeline
    k_gemm<<<(NUSERS + 63) / 64, 128>>>(uf,  wr_w, NUSERS, 0, 0);
    k_gemm<<<(NITEMS + 63) / 64, 128>>>(itf, wr_w, NITEMS, 2, 1);
    k_epi<<<(NUSERS * DIM + 255) / 256, 256>>>(wr_b, NUSERS * DIM,
                                               (double)NUSERS * NFEATS, 0, 4, 0);
    k_epi<<<(NITEMS * DIM + 255) / 256, 256>>>(wr_b, NITEMS * DIM,
                                               (double)NITEMS * NFEATS, 2, 6, 1);
    k_fusion<<<(NUSERS * DIM + 255) / 256, 256>>>(uemb, NUSERS * DIM, 4, 0);
    k_fusion<<<(NITEMS * DIM + 255) / 256, 256>>>(iemb, NITEMS * DIM, 6, 1);

    // SpMMs: register accumulation, no atomics
    const int spmm_grid = (NUSERS * 8 + 255) / 256;
    k_spmm_csr<<<spmm_grid, 256>>>(0, 0, 0);   // g_last = UI @ item_fus
    k_spmm_csr<<<spmm_grid, 256>>>(1, 1, 0);   // g_h1   = S @ user_fus
    k_spmm_csr<<<spmm_grid, 256>>>(1, 2, 1);   // g_last += S @ h1

    k_pred<<<(NPAIRS + 255) / 256, 256>>>(uidx, iidx, out, out_size);
}

// round 11
// speedup vs baseline: 1.8949x; 1.8949x over previous
#include <cuda_runtime.h>
#include <math.h>

#define NUSERS 100000
#define NITEMS 50000
#define NFEATS 512
#define DIM 32
#define ESOC 3200000
#define EUI 3200000
#define NPAIRS 1000000

// ---------------- scratch (device globals; no allocs allowed) ----------------
__device__ double g_red[8];            // [0,1]=uf sum/sq [2,3]=itf [4,5]=usig [6,7]=isig
__device__ float  g_colsum[DIM];
__device__ float  g_user_sig[NUSERS * DIM];
__device__ float  g_item_sig[NITEMS * DIM];
__device__ float  g_user_fus[NUSERS * DIM];
__device__ float  g_item_fus[NITEMS * DIM];
__device__ float  g_h1[NUSERS * DIM];
__device__ float  g_last[NUSERS * DIM];

// ---------------- init ----------------
__global__ void k_init() {
    int i = blockIdx.x * blockDim.x + threadIdx.x;
    float4 z = make_float4(0.f, 0.f, 0.f, 0.f);
    const int n4 = NUSERS * DIM / 4;
    if (i < n4) {
        reinterpret_cast<float4*>(g_h1)[i]   = z;
        reinterpret_cast<float4*>(g_last)[i] = z;
    }
    if (i < 8) g_red[i] = 0.0;
}

// ---------------- column sums of W ----------------
__global__ void k_colsum(const float* __restrict__ W) {
    __shared__ float s[8][DIM];
    int c = threadIdx.x & 31;
    int g = threadIdx.x >> 5;
    float acc = 0.f;
    for (int k = g; k < NFEATS; k += 8) acc += W[k * DIM + c];
    s[g][c] = acc;
    __syncthreads();
    if (g == 0) {
        float t = 0.f;
#pragma unroll
        for (int j = 0; j < 8; j++) t += s[j][c];
        g_colsum[c] = t;
    }
}

// ---------------- GEMM (proven): 64x32 tile, 4x4 per thread, fused stats ----------------
__global__ __launch_bounds__(128) void k_gemm(const float* __restrict__ F,
                                              const float* __restrict__ W,
                                              int M, int redIdx, int outSel) {
    __shared__ float sF[64][33];
    __shared__ float sW[32][36];
    float* __restrict__ out = outSel ? g_item_sig : g_user_sig;

    int t  = threadIdx.x;
    int tc = t & 7;
    int tr = t >> 3;
    int row0 = blockIdx.x * 64;

    float acc[4][4] = {};
    float lsum = 0.f, lsq = 0.f;

    for (int kt = 0; kt < NFEATS / 32; ++kt) {
        int k0 = kt * 32;
#pragma unroll
        for (int i = 0; i < 4; ++i) {
            int fi = t + i * 128;
            int r = fi >> 3, kq = fi & 7;
            float4 v = make_float4(0.f, 0.f, 0.f, 0.f);
            int grow = row0 + r;
            if (grow < M)
                v = *reinterpret_cast<const float4*>(&F[(size_t)grow * NFEATS + k0 + kq * 4]);
            sF[r][kq * 4 + 0] = v.x; sF[r][kq * 4 + 1] = v.y;
            sF[r][kq * 4 + 2] = v.z; sF[r][kq * 4 + 3] = v.w;
            lsum += v.x + v.y + v.z + v.w;
            lsq  += v.x * v.x + v.y * v.y + v.z * v.z + v.w * v.w;
        }
#pragma unroll
        for (int i = 0; i < 2; ++i) {
            int fi = t + i * 128;
            int kr = fi >> 3, kq = fi & 7;
            float4 w = *reinterpret_cast<const float4*>(&W[(size_t)(k0 + kr) * DIM + kq * 4]);
            sW[kr][kq * 4 + 0] = w.x; sW[kr][kq * 4 + 1] = w.y;
            sW[kr][kq * 4 + 2] = w.z; sW[kr][kq * 4 + 3] = w.w;
        }
        __syncthreads();
#pragma unroll
        for (int k = 0; k < 32; ++k) {
            float4 w = *reinterpret_cast<float4*>(&sW[k][tc * 4]);
            float f0 = sF[tr * 4 + 0][k];
            float f1 = sF[tr * 4 + 1][k];
            float f2 = sF[tr * 4 + 2][k];
            float f3 = sF[tr * 4 + 3][k];
            acc[0][0] += f0 * w.x; acc[0][1] += f0 * w.y; acc[0][2] += f0 * w.z; acc[0][3] += f0 * w.w;
            acc[1][0] += f1 * w.x; acc[1][1] += f1 * w.y; acc[1][2] += f1 * w.z; acc[1][3] += f1 * w.w;
            acc[2][0] += f2 * w.x; acc[2][1] += f2 * w.y; acc[2][2] += f2 * w.z; acc[2][3] += f2 * w.w;
            acc[3][0] += f3 * w.x; acc[3][1] += f3 * w.y; acc[3][2] += f3 * w.z; acc[3][3] += f3 * w.w;
        }
        __syncthreads();
    }

#pragma unroll
    for (int o = 16; o; o >>= 1) {
        lsum += __shfl_down_sync(0xffffffffu, lsum, o);
        lsq  += __shfl_down_sync(0xffffffffu, lsq, o);
    }
    __shared__ double sred[4][2];
    int wid = t >> 5, lane = t & 31;
    if (lane == 0) { sred[wid][0] = (double)lsum; sred[wid][1] = (double)lsq; }
    __syncthreads();
    if (t == 0) {
        double a = 0.0, b = 0.0;
#pragma unroll
        for (int j = 0; j < 4; j++) { a += sred[j][0]; b += sred[j][1]; }
        atomicAdd(&g_red[redIdx], a);
        atomicAdd(&g_red[redIdx + 1], b);
    }

#pragma unroll
    for (int i = 0; i < 4; ++i) {
        int grow = row0 + tr * 4 + i;
        if (grow < M) {
            float4 o4 = make_float4(acc[i][0], acc[i][1], acc[i][2], acc[i][3]);
            *reinterpret_cast<float4*>(&out[(size_t)grow * DIM + tc * 4]) = o4;
        }
    }
}

// ---------------- epilogue ----------------
__global__ void k_epi(const float* __restrict__ b, int n, double Nfeat,
                      int si, int so, int sel) {
    float* __restrict__ sig = sel ? g_item_sig : g_user_sig;
    double fsum = g_red[si], fsq = g_red[si + 1];
    double mean = fsum / Nfeat;
    double var  = (fsq - fsum * fsum / Nfeat) / (Nfeat - 1.0);
    float inv_s = (float)(1.0 / sqrt(var));
    float mis   = (float)mean * inv_s;

    int i = blockIdx.x * blockDim.x + threadIdx.x;
    double lsum = 0.0, lsq = 0.0;
    if (i < n) {
        int j = i & (DIM - 1);
        float x = sig[i] * inv_s + b[j] - mis * g_colsum[j];
        float v = 1.f / (1.f + expf(-x));
        sig[i] = v;
        lsum = v;
        lsq  = (double)v * v;
    }
#pragma unroll
    for (int o = 16; o; o >>= 1) {
        lsum += __shfl_down_sync(0xffffffffu, lsum, o);
        lsq  += __shfl_down_sync(0xffffffffu, lsq, o);
    }
    __shared__ double sred[8][2];
    int wid = threadIdx.x >> 5, lane = threadIdx.x & 31;
    if (lane == 0) { sred[wid][0] = lsum; sred[wid][1] = lsq; }
    __syncthreads();
    if (threadIdx.x == 0) {
        double a = 0.0, c = 0.0;
#pragma unroll
        for (int j = 0; j < 8; j++) { a += sred[j][0]; c += sred[j][1]; }
        atomicAdd(&g_red[so], a);
        atomicAdd(&g_red[so + 1], c);
    }
}

// ---------------- fusion ----------------
__global__ void k_fusion(const float* __restrict__ emb, int n, int si, int sel) {
    const float* __restrict__ sig = sel ? g_item_sig : g_user_sig;
    float* __restrict__ fus = sel ? g_item_fus : g_user_fus;
    double s0 = g_red[si], s1 = g_red[si + 1];
    double N = (double)n;
    double mean = s0 / N;
    double var  = (s1 - s0 * s0 / N) / (N - 1.0);
    float inv = (float)(1.0 / sqrt(var));
    float m   = (float)mean;
    int i = blockIdx.x * blockDim.x + threadIdx.x;
    if (i < n) fus[i] = (sig[i] - m) * inv + emb[i];
}

// ---------------- SpMM: smem-staged, straight-line batch of 4, no guards ----------------
// REQUIRES nE % SPMM_EB == 0 (holds: 3.2M / 1024). All blocks full.
#define SPMM_EB 1024
__global__ __launch_bounds__(256) void k_spmm(const int* __restrict__ rows,
                                              const int* __restrict__ cols,
                                              const float* __restrict__ vals,
                                              int selX, int selOut) {
    __shared__ int   sr[SPMM_EB];
    __shared__ int   sc[SPMM_EB];
    __shared__ float sv[SPMM_EB];
    const float* __restrict__ X =
        (selX == 0) ? g_item_fus : (selX == 1) ? g_user_fus : g_h1;
    float* __restrict__ OUT = selOut ? g_h1 : g_last;

    int base = blockIdx.x * SPMM_EB;
#pragma unroll
    for (int i = 0; i < 4; ++i) {
        int idx = threadIdx.x + i * 256;
        sr[idx] = rows[base + idx];
        sc[idx] = cols[base + idx];
        sv[idx] = vals[base + idx];
    }
    __syncthreads();

    int sub = threadIdx.x & 7;
    int grp = threadIdx.x >> 3;                // 32 groups of 8 threads
#pragma unroll
    for (int pass = 0; pass < SPMM_EB / 128; ++pass) {   // 8 passes, 4 edges each
        int e = grp + pass * 128;
        int r0 = sr[e],       c0 = sc[e];       float v0 = sv[e];
        int r1 = sr[e + 32],  c1 = sc[e + 32];  float v1 = sv[e + 32];
        int r2 = sr[e + 64],  c2 = sc[e + 64];  float v2 = sv[e + 64];
        int r3 = sr[e + 96],  c3 = sc[e + 96];  float v3 = sv[e + 96];
        float4 x0 = *reinterpret_cast<const float4*>(&X[(size_t)c0 * DIM + sub * 4]);
        float4 x1 = *reinterpret_cast<const float4*>(&X[(size_t)c1 * DIM + sub * 4]);
        float4 x2 = *reinterpret_cast<const float4*>(&X[(size_t)c2 * DIM + sub * 4]);
        float4 x3 = *reinterpret_cast<const float4*>(&X[(size_t)c3 * DIM + sub * 4]);
        float* p0 = &OUT[(size_t)r0 * DIM + sub * 4];
        float* p1 = &OUT[(size_t)r1 * DIM + sub * 4];
        float* p2 = &OUT[(size_t)r2 * DIM + sub * 4];
        float* p3 = &OUT[(size_t)r3 * DIM + sub * 4];
        asm volatile("red.global.add.v4.f32 [%0], {%1,%2,%3,%4};"
                     :: "l"(p0), "f"(x0.x * v0), "f"(x0.y * v0), "f"(x0.z * v0), "f"(x0.w * v0));
        asm volatile("red.global.add.v4.f32 [%0], {%1,%2,%3,%4};"
                     :: "l"(p1), "f"(x1.x * v1), "f"(x1.y * v1), "f"(x1.z * v1), "f"(x1.w * v1));
        asm volatile("red.global.add.v4.f32 [%0], {%1,%2,%3,%4};"
                     :: "l"(p2), "f"(x2.x * v2), "f"(x2.y * v2), "f"(x2.z * v2), "f"(x2.w * v2));
        asm volatile("red.global.add.v4.f32 [%0], {%1,%2,%3,%4};"
                     :: "l"(p3), "f"(x3.x * v3), "f"(x3.y * v3), "f"(x3.z * v3), "f"(x3.w * v3));
    }
}

// ---------------- prediction: smem-staged, batch of 2 (straight-line, guarded only in tail) ----------------
__global__ __launch_bounds__(256) void k_pred(const int* __restrict__ ui,
                                              const int* __restrict__ ii,
                                              float* __restrict__ out, int out_size) {
    __shared__ int su[512];
    __shared__ int sI[512];
    int base = blockIdx.x << 9;
    int t = threadIdx.x;
    int n = NPAIRS - base; if (n > 512) n = 512;
    for (int i = t; i < n; i += 256) { su[i] = ui[base + i]; sI[i] = ii[base + i]; }
    __syncthreads();

    int sub = t & 7, grp = t >> 3;
    if (n == 512) {
        // full block: no guards, 2-wide batch
#pragma unroll
        for (int pass = 0; pass < 8; ++pass) {
            int p = grp + pass * 64;
            int u0 = su[p],      i0 = sI[p];
            int u1 = su[p + 32], i1 = sI[p + 32];
            float4 a0 = *reinterpret_cast<const float4*>(&g_last[(size_t)u0 * DIM + sub * 4]);
            float4 b0 = *reinterpret_cast<const float4*>(&g_item_fus[(size_t)i0 * DIM + sub * 4]);
            float4 a1 = *reinterpret_cast<const float4*>(&g_last[(size_t)u1 * DIM + sub * 4]);
            float4 b1 = *reinterpret_cast<const float4*>(&g_item_fus[(size_t)i1 * DIM + sub * 4]);
            float d0 = a0.x * b0.x + a0.y * b0.y + a0.z * b0.z + a0.w * b0.w;
            float d1 = a1.x * b1.x + a1.y * b1.y + a1.z * b1.z + a1.w * b1.w;
#pragma unroll
            for (int o = 4; o; o >>= 1) {
                d0 += __shfl_down_sync(0xffffffffu, d0, o, 8);
                d1 += __shfl_down_sync(0xffffffffu, d1, o, 8);
            }
            if (sub == 0) {
                int gp0 = base + p, gp1 = base + p + 32;
                out[gp0] = d0;
                out[NPAIRS + gp0] = 1.f / (1.f + expf(-d0));
                out[gp1] = d1;
                out[NPAIRS + gp1] = 1.f / (1.f + expf(-d1));
            }
        }
    } else {
        for (int p = grp; p < n; p += 32) {
            int u  = su[p];
            int it = sI[p];
            float4 a = *reinterpret_cast<const float4*>(&g_last[(size_t)u * DIM + sub * 4]);
            float4 b = *reinterpret_cast<const float4*>(&g_item_fus[(size_t)it * DIM + sub * 4]);
            float d = a.x * b.x + a.y * b.y + a.z * b.z + a.w * b.w;
#pragma unroll
            for (int o = 4; o; o >>= 1) d += __shfl_down_sync(0xffffffffu, d, o, 8);
            if (sub == 0) {
                int gp = base + p;
                if (gp < out_size) out[gp] = d;
                if (NPAIRS + gp < out_size) out[NPAIRS + gp] = 1.f / (1.f + expf(-d));
            }
        }
    }
}

// ---------------- launch ----------------
extern "C" void kernel_launch(void* const* d_in, const int* in_sizes, int n_in,
                              void* d_out, int out_size) {
    const float* uf    = (const float*)d_in[0];
    const float* itf   = (const float*)d_in[1];
    const float* uemb  = (const float*)d_in[2];
    const float* iemb  = (const float*)d_in[3];
    const float* wr_w  = (const float*)d_in[4];
    const float* wr_b  = (const float*)d_in[5];
    const int*   srows = (const int*)d_in[6];
    const int*   scols = (const int*)d_in[7];
    const float* svals = (const float*)d_in[8];
    const int*   urows = (const int*)d_in[9];
    const int*   ucols = (const int*)d_in[10];
    const float* uvals = (const float*)d_in[11];
    const int*   uidx  = (const int*)d_in[12];
    const int*   iidx  = (const int*)d_in[13];
    float* out = (float*)d_out;

    k_init<<<(NUSERS * DIM / 4 + 255) / 256, 256>>>();
    k_colsum<<<1, 256>>>(wr_w);
    k_gemm<<<(NUSERS + 63) / 64, 128>>>(uf,  wr_w, NUSERS, 0, 0);
    k_gemm<<<(NITEMS + 63) / 64, 128>>>(itf, wr_w, NITEMS, 2, 1);
    k_epi<<<(NUSERS * DIM + 255) / 256, 256>>>(wr_b, NUSERS * DIM,
                                               (double)NUSERS * NFEATS, 0, 4, 0);
    k_epi<<<(NITEMS * DIM + 255) / 256, 256>>>(wr_b, NITEMS * DIM,
                                               (double)NITEMS * NFEATS, 2, 6, 1);
    k_fusion<<<(NUSERS * DIM + 255) / 256, 256>>>(uemb, NUSERS * DIM, 4, 0);
    k_fusion<<<(NITEMS * DIM + 255) / 256, 256>>>(iemb, NITEMS * DIM, 6, 1);
    k_spmm<<<EUI  / SPMM_EB, 256>>>(urows, ucols, uvals, 0, 0);
    k_spmm<<<ESOC / SPMM_EB, 256>>>(srows, scols, svals, 1, 1);
    k_spmm<<<ESOC / SPMM_EB, 256>>>(srows, scols, svals, 2, 0);
    k_pred<<<(NPAIRS + 511) / 512, 256>>>(uidx, iidx, out, out_size);
}

// round 12
// speedup vs baseline: 2.2036x; 1.1629x over previous
#include <cuda_runtime.h>
#include <math.h>

#define NUSERS 100000
#define NITEMS 50000
#define NFEATS 512
#define DIM 32
#define ESOC 3200000
#define EUI 3200000
#define NPAIRS 1000000

// ---------------- scratch (device globals; no allocs allowed) ----------------
__device__ double g_red[8];            // [0,1]=uf sum/sq [2,3]=itf [4,5]=usig [6,7]=isig
__device__ float  g_colsum[DIM];
__device__ float  g_user_sig[NUSERS * DIM];
__device__ float  g_item_sig[NITEMS * DIM];
__device__ float  g_user_fus[NUSERS * DIM];
__device__ float  g_item_fus[NITEMS * DIM];
__device__ float  g_h1[NUSERS * DIM];
__device__ float  g_last[NUSERS * DIM];

// ---------------- init ----------------
__global__ void k_init() {
    int i = blockIdx.x * blockDim.x + threadIdx.x;
    float4 z = make_float4(0.f, 0.f, 0.f, 0.f);
    const int n4 = NUSERS * DIM / 4;
    if (i < n4) {
        reinterpret_cast<float4*>(g_h1)[i]   = z;
        reinterpret_cast<float4*>(g_last)[i] = z;
    }
    if (i < 8) g_red[i] = 0.0;
}

// ---------------- column sums of W ----------------
__global__ void k_colsum(const float* __restrict__ W) {
    __shared__ float s[8][DIM];
    int c = threadIdx.x & 31;
    int g = threadIdx.x >> 5;
    float acc = 0.f;
    for (int k = g; k < NFEATS; k += 8) acc += W[k * DIM + c];
    s[g][c] = acc;
    __syncthreads();
    if (g == 0) {
        float t = 0.f;
#pragma unroll
        for (int j = 0; j < 8; j++) t += s[j][c];
        g_colsum[c] = t;
    }
}

// ---------------- GEMM (proven): 64x32 tile, 4x4 per thread, fused stats ----------------
__global__ __launch_bounds__(128) void k_gemm(const float* __restrict__ F,
                                              const float* __restrict__ W,
                                              int M, int redIdx, int outSel) {
    __shared__ float sF[64][33];
    __shared__ float sW[32][36];
    float* __restrict__ out = outSel ? g_item_sig : g_user_sig;

    int t  = threadIdx.x;
    int tc = t & 7;
    int tr = t >> 3;
    int row0 = blockIdx.x * 64;

    float acc[4][4] = {};
    float lsum = 0.f, lsq = 0.f;

    for (int kt = 0; kt < NFEATS / 32; ++kt) {
        int k0 = kt * 32;
#pragma unroll
        for (int i = 0; i < 4; ++i) {
            int fi = t + i * 128;
            int r = fi >> 3, kq = fi & 7;
            float4 v = make_float4(0.f, 0.f, 0.f, 0.f);
            int grow = row0 + r;
            if (grow < M)
                v = *reinterpret_cast<const float4*>(&F[(size_t)grow * NFEATS + k0 + kq * 4]);
            sF[r][kq * 4 + 0] = v.x; sF[r][kq * 4 + 1] = v.y;
            sF[r][kq * 4 + 2] = v.z; sF[r][kq * 4 + 3] = v.w;
            lsum += v.x + v.y + v.z + v.w;
            lsq  += v.x * v.x + v.y * v.y + v.z * v.z + v.w * v.w;
        }
#pragma unroll
        for (int i = 0; i < 2; ++i) {
            int fi = t + i * 128;
            int kr = fi >> 3, kq = fi & 7;
            float4 w = *reinterpret_cast<const float4*>(&W[(size_t)(k0 + kr) * DIM + kq * 4]);
            sW[kr][kq * 4 + 0] = w.x; sW[kr][kq * 4 + 1] = w.y;
            sW[kr][kq * 4 + 2] = w.z; sW[kr][kq * 4 + 3] = w.w;
        }
        __syncthreads();
#pragma unroll
        for (int k = 0; k < 32; ++k) {
            float4 w = *reinterpret_cast<float4*>(&sW[k][tc * 4]);
            float f0 = sF[tr * 4 + 0][k];
            float f1 = sF[tr * 4 + 1][k];
            float f2 = sF[tr * 4 + 2][k];
            float f3 = sF[tr * 4 + 3][k];
            acc[0][0] += f0 * w.x; acc[0][1] += f0 * w.y; acc[0][2] += f0 * w.z; acc[0][3] += f0 * w.w;
            acc[1][0] += f1 * w.x; acc[1][1] += f1 * w.y; acc[1][2] += f1 * w.z; acc[1][3] += f1 * w.w;
            acc[2][0] += f2 * w.x; acc[2][1] += f2 * w.y; acc[2][2] += f2 * w.z; acc[2][3] += f2 * w.w;
            acc[3][0] += f3 * w.x; acc[3][1] += f3 * w.y; acc[3][2] += f3 * w.z; acc[3][3] += f3 * w.w;
        }
        __syncthreads();
    }

#pragma unroll
    for (int o = 16; o; o >>= 1) {
        lsum += __shfl_down_sync(0xffffffffu, lsum, o);
        lsq  += __shfl_down_sync(0xffffffffu, lsq, o);
    }
    __shared__ double sred[4][2];
    int wid = t >> 5, lane = t & 31;
    if (lane == 0) { sred[wid][0] = (double)lsum; sred[wid][1] = (double)lsq; }
    __syncthreads();
    if (t == 0) {
        double a = 0.0, b = 0.0;
#pragma unroll
        for (int j = 0; j < 4; j++) { a += sred[j][0]; b += sred[j][1]; }
        atomicAdd(&g_red[redIdx], a);
        atomicAdd(&g_red[redIdx + 1], b);
    }

#pragma unroll
    for (int i = 0; i < 4; ++i) {
        int grow = row0 + tr * 4 + i;
        if (grow < M) {
            float4 o4 = make_float4(acc[i][0], acc[i][1], acc[i][2], acc[i][3]);
            *reinterpret_cast<float4*>(&out[(size_t)grow * DIM + tc * 4]) = o4;
        }
    }
}

// ---------------- epilogue: fp32 local reductions ----------------
__global__ void k_epi(const float* __restrict__ b, int n, double Nfeat,
                      int si, int so, int sel) {
    float* __restrict__ sig = sel ? g_item_sig : g_user_sig;
    double fsum = g_red[si], fsq = g_red[si + 1];
    double mean = fsum / Nfeat;
    double var  = (fsq - fsum * fsum / Nfeat) / (Nfeat - 1.0);
    float inv_s = (float)(1.0 / sqrt(var));
    float mis   = (float)mean * inv_s;

    int i = blockIdx.x * blockDim.x + threadIdx.x;
    float lsum = 0.f, lsq = 0.f;
    if (i < n) {
        int j = i & (DIM - 1);
        float x = sig[i] * inv_s + b[j] - mis * g_colsum[j];
        float v = 1.f / (1.f + expf(-x));
        sig[i] = v;
        lsum = v;
        lsq  = v * v;
    }
#pragma unroll
    for (int o = 16; o; o >>= 1) {
        lsum += __shfl_down_sync(0xffffffffu, lsum, o);
        lsq  += __shfl_down_sync(0xffffffffu, lsq, o);
    }
    __shared__ double sred[8][2];
    int wid = threadIdx.x >> 5, lane = threadIdx.x & 31;
    if (lane == 0) { sred[wid][0] = (double)lsum; sred[wid][1] = (double)lsq; }
    __syncthreads();
    if (threadIdx.x == 0) {
        double a = 0.0, c = 0.0;
#pragma unroll
        for (int j = 0; j < 8; j++) { a += sred[j][0]; c += sred[j][1]; }
        atomicAdd(&g_red[so], a);
        atomicAdd(&g_red[so + 1], c);
    }
}

// ---------------- fusion ----------------
__global__ void k_fusion(const float* __restrict__ emb, int n, int si, int sel) {
    const float* __restrict__ sig = sel ? g_item_sig : g_user_sig;
    float* __restrict__ fus = sel ? g_item_fus : g_user_fus;
    double s0 = g_red[si], s1 = g_red[si + 1];
    double N = (double)n;
    double mean = s0 / N;
    double var  = (s1 - s0 * s0 / N) / (N - 1.0);
    float inv = (float)(1.0 / sqrt(var));
    float m   = (float)mean;
    int i = blockIdx.x * blockDim.x + threadIdx.x;
    if (i < n) fus[i] = (sig[i] - m) * inv + emb[i];
}

// ---------------- SpMM: smem-staged, straight-line batch of 4 ----------------
// REQUIRES nE % SPMM_EB == 0 (holds: 3.2M / 1024).
#define SPMM_EB 1024
__global__ __launch_bounds__(256) void k_spmm(const int* __restrict__ rows,
                                              const int* __restrict__ cols,
                                              const float* __restrict__ vals,
                                              int selX, int selOut) {
    __shared__ int   sr[SPMM_EB];
    __shared__ int   sc[SPMM_EB];
    __shared__ float sv[SPMM_EB];
    const float* __restrict__ X =
        (selX == 0) ? g_item_fus : (selX == 1) ? g_user_fus : g_h1;
    float* __restrict__ OUT = selOut ? g_h1 : g_last;

    int base = blockIdx.x * SPMM_EB;
#pragma unroll
    for (int i = 0; i < 4; ++i) {
        int idx = threadIdx.x + i * 256;
        sr[idx] = rows[base + idx];
        sc[idx] = cols[base + idx];
        sv[idx] = vals[base + idx];
    }
    __syncthreads();

    int sub = threadIdx.x & 7;
    int grp = threadIdx.x >> 3;
#pragma unroll
    for (int pass = 0; pass < SPMM_EB / 128; ++pass) {
        int e = grp + pass * 128;
        int r0 = sr[e],       c0 = sc[e];       float v0 = sv[e];
        int r1 = sr[e + 32],  c1 = sc[e + 32];  float v1 = sv[e + 32];
        int r2 = sr[e + 64],  c2 = sc[e + 64];  float v2 = sv[e + 64];
        int r3 = sr[e + 96],  c3 = sc[e + 96];  float v3 = sv[e + 96];
        float4 x0 = *reinterpret_cast<const float4*>(&X[(size_t)c0 * DIM + sub * 4]);
        float4 x1 = *reinterpret_cast<const float4*>(&X[(size_t)c1 * DIM + sub * 4]);
        float4 x2 = *reinterpret_cast<const float4*>(&X[(size_t)c2 * DIM + sub * 4]);
        float4 x3 = *reinterpret_cast<const float4*>(&X[(size_t)c3 * DIM + sub * 4]);
        float* p0 = &OUT[(size_t)r0 * DIM + sub * 4];
        float* p1 = &OUT[(size_t)r1 * DIM + sub * 4];
        float* p2 = &OUT[(size_t)r2 * DIM + sub * 4];
        float* p3 = &OUT[(size_t)r3 * DIM + sub * 4];
        asm volatile("red.global.add.v4.f32 [%0], {%1,%2,%3,%4};"
                     :: "l"(p0), "f"(x0.x * v0), "f"(x0.y * v0), "f"(x0.z * v0), "f"(x0.w * v0));
        asm volatile("red.global.add.v4.f32 [%0], {%1,%2,%3,%4};"
                     :: "l"(p1), "f"(x1.x * v1), "f"(x1.y * v1), "f"(x1.z * v1), "f"(x1.w * v1));
        asm volatile("red.global.add.v4.f32 [%0], {%1,%2,%3,%4};"
                     :: "l"(p2), "f"(x2.x * v2), "f"(x2.y * v2), "f"(x2.z * v2), "f"(x2.w * v2));
        asm volatile("red.global.add.v4.f32 [%0], {%1,%2,%3,%4};"
                     :: "l"(p3), "f"(x3.x * v3), "f"(x3.y * v3), "f"(x3.z * v3), "f"(x3.w * v3));
    }
}

// ---------------- prediction ----------------
__global__ __launch_bounds__(256) void k_pred(const int* __restrict__ ui,
                                              const int* __restrict__ ii,
                                              float* __restrict__ out, int out_size) {
    __shared__ int su[512];
    __shared__ int sI[512];
    int base = blockIdx.x << 9;
    int t = threadIdx.x;
    int n = NPAIRS - base; if (n > 512) n = 512;
    for (int i = t; i < n; i += 256) { su[i] = ui[base + i]; sI[i] = ii[base + i]; }
    __syncthreads();

    int sub = t & 7, grp = t >> 3;
    if (n == 512) {
#pragma unroll
        for (int pass = 0; pass < 8; ++pass) {
            int p = grp + pass * 64;
            int u0 = su[p],      i0 = sI[p];
            int u1 = su[p + 32], i1 = sI[p + 32];
            float4 a0 = *reinterpret_cast<const float4*>(&g_last[(size_t)u0 * DIM + sub * 4]);
            float4 b0 = *reinterpret_cast<const float4*>(&g_item_fus[(size_t)i0 * DIM + sub * 4]);
            float4 a1 = *reinterpret_cast<const float4*>(&g_last[(size_t)u1 * DIM + sub * 4]);
            float4 b1 = *reinterpret_cast<const float4*>(&g_item_fus[(size_t)i1 * DIM + sub * 4]);
            float d0 = a0.x * b0.x + a0.y * b0.y + a0.z * b0.z + a0.w * b0.w;
            float d1 = a1.x * b1.x + a1.y * b1.y + a1.z * b1.z + a1.w * b1.w;
#pragma unroll
            for (int o = 4; o; o >>= 1) {
                d0 += __shfl_down_sync(0xffffffffu, d0, o, 8);
                d1 += __shfl_down_sync(0xffffffffu, d1, o, 8);
            }
            if (sub == 0) {
                int gp0 = base + p, gp1 = base + p + 32;
                out[gp0] = d0;
                out[NPAIRS + gp0] = 1.f / (1.f + expf(-d0));
                out[gp1] = d1;
                out[NPAIRS + gp1] = 1.f / (1.f + expf(-d1));
            }
        }
    } else {
        for (int p = grp; p < n; p += 32) {
            int u  = su[p];
            int it = sI[p];
            float4 a = *reinterpret_cast<const float4*>(&g_last[(size_t)u * DIM + sub * 4]);
            float4 b = *reinterpret_cast<const float4*>(&g_item_fus[(size_t)it * DIM + sub * 4]);
            float d = a.x * b.x + a.y * b.y + a.z * b.z + a.w * b.w;
#pragma unroll
            for (int o = 4; o; o >>= 1) d += __shfl_down_sync(0xffffffffu, d, o, 8);
            if (sub == 0) {
                int gp = base + p;
                if (gp < out_size) out[gp] = d;
                if (NPAIRS + gp < out_size) out[NPAIRS + gp] = 1.f / (1.f + expf(-d));
            }
        }
    }
}

// ---------------- launch: fork/join across two side streams ----------------
extern "C" void kernel_launch(void* const* d_in, const int* in_sizes, int n_in,
                              void* d_out, int out_size) {
    const float* uf    = (const float*)d_in[0];
    const float* itf   = (const float*)d_in[1];
    const float* uemb  = (const float*)d_in[2];
    const float* iemb  = (const float*)d_in[3];
    const float* wr_w  = (const float*)d_in[4];
    const float* wr_b  = (const float*)d_in[5];
    const int*   srows = (const int*)d_in[6];
    const int*   scols = (const int*)d_in[7];
    const float* svals = (const float*)d_in[8];
    const int*   urows = (const int*)d_in[9];
    const int*   ucols = (const int*)d_in[10];
    const float* uvals = (const float*)d_in[11];
    const int*   uidx  = (const int*)d_in[12];
    const int*   iidx  = (const int*)d_in[13];
    float* out = (float*)d_out;

    // one-time stream/event setup (host-side resources only; graph structure
    // is identical on every call)
    static cudaStream_t sA = 0, sB = 0;
    static cudaEvent_t  eFork = 0, eA = 0, eB = 0;
    if (sA == 0) {
        cudaStreamCreateWithFlags(&sA, cudaStreamNonBlocking);
        cudaStreamCreateWithFlags(&sB, cudaStreamNonBlocking);
        cudaEventCreateWithFlags(&eFork, cudaEventDisableTiming);
        cudaEventCreateWithFlags(&eA, cudaEventDisableTiming);
        cudaEventCreateWithFlags(&eB, cudaEventDisableTiming);
    }

    // prologue on origin stream
    k_init<<<(NUSERS * DIM / 4 + 255) / 256, 256>>>();
    k_colsum<<<1, 256>>>(wr_w);
    cudaEventRecord(eFork, 0);
    cudaStreamWaitEvent(sA, eFork, 0);
    cudaStreamWaitEvent(sB, eFork, 0);

    // stream A: item chain -> UI SpMM (atomics into g_last)
    k_gemm<<<(NITEMS + 63) / 64, 128, 0, sA>>>(itf, wr_w, NITEMS, 2, 1);
    k_epi<<<(NITEMS * DIM + 255) / 256, 256, 0, sA>>>(wr_b, NITEMS * DIM,
                                                      (double)NITEMS * NFEATS, 2, 6, 1);
    k_fusion<<<(NITEMS * DIM + 255) / 256, 256, 0, sA>>>(iemb, NITEMS * DIM, 6, 1);
    k_spmm<<<EUI / SPMM_EB, 256, 0, sA>>>(urows, ucols, uvals, 0, 0);

    // stream B: user chain -> soc1 -> soc2 (soc2 atomics into g_last, commutes with A)
    k_gemm<<<(NUSERS + 63) / 64, 128, 0, sB>>>(uf, wr_w, NUSERS, 0, 0);
    k_epi<<<(NUSERS * DIM + 255) / 256, 256, 0, sB>>>(wr_b, NUSERS * DIM,
                                                      (double)NUSERS * NFEATS, 0, 4, 0);
    k_fusion<<<(NUSERS * DIM + 255) / 256, 256, 0, sB>>>(uemb, NUSERS * DIM, 4, 0);
    k_spmm<<<ESOC / SPMM_EB, 256, 0, sB>>>(srows, scols, svals, 1, 1);
    k_spmm<<<ESOC / SPMM_EB, 256, 0, sB>>>(srows, scols, svals, 2, 0);

    // join
    cudaEventRecord(eA, sA);
    cudaEventRecord(eB, sB);
    cudaStreamWaitEvent(0, eA, 0);
    cudaStreamWaitEvent(0, eB, 0);
    k_pred<<<(NPAIRS + 511) / 512, 256>>>(uidx, iidx, out, out_size);
}

// round 13
// speedup vs baseline: 5.5303x; 2.5096x over previous
#include <cuda_runtime.h>
#include <math.h>

#define NUSERS 100000
#define NITEMS 50000
#define NFEATS 512
#define DIM 32
#define ESOC 3200000
#define EUI 3200000
#define NPAIRS 1000000

// ---------------- scratch (device globals; no allocs allowed) ----------------
__device__ double g_red[8];            // [0,1]=uf sum/sq [2,3]=itf [4,5]=usig [6,7]=isig
__device__ float  g_scal[8];           // [0,1]=(inv_s,mis)_u [2,3]=(inv_s,mis)_i [4,5]=(m,inv)_usig [6,7]=(m,inv)_isig
__device__ float  g_colsum[DIM];
__device__ float  g_user_sig[NUSERS * DIM];
__device__ float  g_item_sig[NITEMS * DIM];
__device__ float  g_user_fus[NUSERS * DIM];
__device__ float  g_item_fus[NITEMS * DIM];
__device__ float  g_h1[NUSERS * DIM];
__device__ float  g_last[NUSERS * DIM];

// ---------------- init ----------------
__global__ void k_init() {
    int i = blockIdx.x * blockDim.x + threadIdx.x;
    float4 z = make_float4(0.f, 0.f, 0.f, 0.f);
    const int n4 = NUSERS * DIM / 4;
    if (i < n4) {
        reinterpret_cast<float4*>(g_h1)[i]   = z;
        reinterpret_cast<float4*>(g_last)[i] = z;
    }
    if (i < 8) g_red[i] = 0.0;
}

// ---------------- column sums of W ----------------
__global__ void k_colsum(const float* __restrict__ W) {
    __shared__ float s[8][DIM];
    int c = threadIdx.x & 31;
    int g = threadIdx.x >> 5;
    float acc = 0.f;
    for (int k = g; k < NFEATS; k += 8) acc += W[k * DIM + c];
    s[g][c] = acc;
    __syncthreads();
    if (g == 0) {
        float t = 0.f;
#pragma unroll
        for (int j = 0; j < 8; j++) t += s[j][c];
        g_colsum[c] = t;
    }
}

// ---------------- scalar stats: fp64 ONCE, broadcast floats ----------------
// mode 0: feature stats -> (inv_s, mean*inv_s)   mode 1: sig stats -> (mean, inv_s)
__global__ void k_scal(int si, double N, int mode) {
    double s0 = g_red[si], s1 = g_red[si + 1];
    double mean = s0 / N;
    double var  = (s1 - s0 * s0 / N) / (N - 1.0);
    double inv  = 1.0 / sqrt(var);
    if (mode == 0) {
        g_scal[si]     = (float)inv;
        g_scal[si + 1] = (float)(mean * inv);
    } else {
        g_scal[si]     = (float)mean;
        g_scal[si + 1] = (float)inv;
    }
}

// ---------------- GEMM (proven): 64x32 tile, 4x4 per thread, fused stats ----------------
__global__ __launch_bounds__(128) void k_gemm(const float* __restrict__ F,
                                              const float* __restrict__ W,
                                              int M, int redIdx, int outSel) {
    __shared__ float sF[64][33];
    __shared__ float sW[32][36];
    float* __restrict__ out = outSel ? g_item_sig : g_user_sig;

    int t  = threadIdx.x;
    int tc = t & 7;
    int tr = t >> 3;
    int row0 = blockIdx.x * 64;

    float acc[4][4] = {};
    float lsum = 0.f, lsq = 0.f;

    for (int kt = 0; kt < NFEATS / 32; ++kt) {
        int k0 = kt * 32;
#pragma unroll
        for (int i = 0; i < 4; ++i) {
            int fi = t + i * 128;
            int r = fi >> 3, kq = fi & 7;
            float4 v = make_float4(0.f, 0.f, 0.f, 0.f);
            int grow = row0 + r;
            if (grow < M)
                v = *reinterpret_cast<const float4*>(&F[(size_t)grow * NFEATS + k0 + kq * 4]);
            sF[r][kq * 4 + 0] = v.x; sF[r][kq * 4 + 1] = v.y;
            sF[r][kq * 4 + 2] = v.z; sF[r][kq * 4 + 3] = v.w;
            lsum += v.x + v.y + v.z + v.w;
            lsq  += v.x * v.x + v.y * v.y + v.z * v.z + v.w * v.w;
        }
#pragma unroll
        for (int i = 0; i < 2; ++i) {
            int fi = t + i * 128;
            int kr = fi >> 3, kq = fi & 7;
            float4 w = *reinterpret_cast<const float4*>(&W[(size_t)(k0 + kr) * DIM + kq * 4]);
            sW[kr][kq * 4 + 0] = w.x; sW[kr][kq * 4 + 1] = w.y;
            sW[kr][kq * 4 + 2] = w.z; sW[kr][kq * 4 + 3] = w.w;
        }
        __syncthreads();
#pragma unroll
        for (int k = 0; k < 32; ++k) {
            float4 w = *reinterpret_cast<float4*>(&sW[k][tc * 4]);
            float f0 = sF[tr * 4 + 0][k];
            float f1 = sF[tr * 4 + 1][k];
            float f2 = sF[tr * 4 + 2][k];
            float f3 = sF[tr * 4 + 3][k];
            acc[0][0] += f0 * w.x; acc[0][1] += f0 * w.y; acc[0][2] += f0 * w.z; acc[0][3] += f0 * w.w;
            acc[1][0] += f1 * w.x; acc[1][1] += f1 * w.y; acc[1][2] += f1 * w.z; acc[1][3] += f1 * w.w;
            acc[2][0] += f2 * w.x; acc[2][1] += f2 * w.y; acc[2][2] += f2 * w.z; acc[2][3] += f2 * w.w;
            acc[3][0] += f3 * w.x; acc[3][1] += f3 * w.y; acc[3][2] += f3 * w.z; acc[3][3] += f3 * w.w;
        }
        __syncthreads();
    }

#pragma unroll
    for (int o = 16; o; o >>= 1) {
        lsum += __shfl_down_sync(0xffffffffu, lsum, o);
        lsq  += __shfl_down_sync(0xffffffffu, lsq, o);
    }
    __shared__ double sred[4][2];
    int wid = t >> 5, lane = t & 31;
    if (lane == 0) { sred[wid][0] = (double)lsum; sred[wid][1] = (double)lsq; }
    __syncthreads();
    if (t == 0) {
        double a = 0.0, b = 0.0;
#pragma unroll
        for (int j = 0; j < 4; j++) { a += sred[j][0]; b += sred[j][1]; }
        atomicAdd(&g_red[redIdx], a);
        atomicAdd(&g_red[redIdx + 1], b);
    }

#pragma unroll
    for (int i = 0; i < 4; ++i) {
        int grow = row0 + tr * 4 + i;
        if (grow < M) {
            float4 o4 = make_float4(acc[i][0], acc[i][1], acc[i][2], acc[i][3]);
            *reinterpret_cast<float4*>(&out[(size_t)grow * DIM + tc * 4]) = o4;
        }
    }
}

// ---------------- epilogue: pure fp32, scalars preloaded ----------------
__global__ void k_epi(const float* __restrict__ b, int n, int si, int so, int sel) {
    float* __restrict__ sig = sel ? g_item_sig : g_user_sig;
    float inv_s = g_scal[si];
    float mis   = g_scal[si + 1];

    int i = blockIdx.x * blockDim.x + threadIdx.x;
    float lsum = 0.f, lsq = 0.f;
    if (i < n) {
        int j = i & (DIM - 1);
        float x = sig[i] * inv_s + b[j] - mis * g_colsum[j];
        float v = 1.f / (1.f + expf(-x));
        sig[i] = v;
        lsum = v;
        lsq  = v * v;
    }
#pragma unroll
    for (int o = 16; o; o >>= 1) {
        lsum += __shfl_down_sync(0xffffffffu, lsum, o);
        lsq  += __shfl_down_sync(0xffffffffu, lsq, o);
    }
    __shared__ double sred[8][2];
    int wid = threadIdx.x >> 5, lane = threadIdx.x & 31;
    if (lane == 0) { sred[wid][0] = (double)lsum; sred[wid][1] = (double)lsq; }
    __syncthreads();
    if (threadIdx.x == 0) {
        double a = 0.0, c = 0.0;
#pragma unroll
        for (int j = 0; j < 8; j++) { a += sred[j][0]; c += sred[j][1]; }
        atomicAdd(&g_red[so], a);
        atomicAdd(&g_red[so + 1], c);
    }
}

// ---------------- fusion: pure fp32, scalars preloaded ----------------
__global__ void k_fusion(const float* __restrict__ emb, int n, int si, int sel) {
    const float* __restrict__ sig = sel ? g_item_sig : g_user_sig;
    float* __restrict__ fus = sel ? g_item_fus : g_user_fus;
    float m   = g_scal[si];
    float inv = g_scal[si + 1];
    int i = blockIdx.x * blockDim.x + threadIdx.x;
    if (i < n) fus[i] = (sig[i] - m) * inv + emb[i];
}

// ---------------- SpMM: smem-staged, straight-line batch of 4 ----------------
// REQUIRES nE % SPMM_EB == 0 (holds: 3.2M / 1024).
#define SPMM_EB 1024
__global__ __launch_bounds__(256) void k_spmm(const int* __restrict__ rows,
                                              const int* __restrict__ cols,
                                              const float* __restrict__ vals,
                                              int selX, int selOut) {
    __shared__ int   sr[SPMM_EB];
    __shared__ int   sc[SPMM_EB];
    __shared__ float sv[SPMM_EB];
    const float* __restrict__ X =
        (selX == 0) ? g_item_fus : (selX == 1) ? g_user_fus : g_h1;
    float* __restrict__ OUT = selOut ? g_h1 : g_last;

    int base = blockIdx.x * SPMM_EB;
#pragma unroll
    for (int i = 0; i < 4; ++i) {
        int idx = threadIdx.x + i * 256;
        sr[idx] = rows[base + idx];
        sc[idx] = cols[base + idx];
        sv[idx] = vals[base + idx];
    }
    __syncthreads();

    int sub = threadIdx.x & 7;
    int grp = threadIdx.x >> 3;
#pragma unroll
    for (int pass = 0; pass < SPMM_EB / 128; ++pass) {
        int e = grp + pass * 128;
        int r0 = sr[e],       c0 = sc[e];       float v0 = sv[e];
        int r1 = sr[e + 32],  c1 = sc[e + 32];  float v1 = sv[e + 32];
        int r2 = sr[e + 64],  c2 = sc[e + 64];  float v2 = sv[e + 64];
        int r3 = sr[e + 96],  c3 = sc[e + 96];  float v3 = sv[e + 96];
        float4 x0 = *reinterpret_cast<const float4*>(&X[(size_t)c0 * DIM + sub * 4]);
        float4 x1 = *reinterpret_cast<const float4*>(&X[(size_t)c1 * DIM + sub * 4]);
        float4 x2 = *reinterpret_cast<const float4*>(&X[(size_t)c2 * DIM + sub * 4]);
        float4 x3 = *reinterpret_cast<const float4*>(&X[(size_t)c3 * DIM + sub * 4]);
        float* p0 = &OUT[(size_t)r0 * DIM + sub * 4];
        float* p1 = &OUT[(size_t)r1 * DIM + sub * 4];
        float* p2 = &OUT[(size_t)r2 * DIM + sub * 4];
        float* p3 = &OUT[(size_t)r3 * DIM + sub * 4];
        asm volatile("red.global.add.v4.f32 [%0], {%1,%2,%3,%4};"
                     :: "l"(p0), "f"(x0.x * v0), "f"(x0.y * v0), "f"(x0.z * v0), "f"(x0.w * v0));
        asm volatile("red.global.add.v4.f32 [%0], {%1,%2,%3,%4};"
                     :: "l"(p1), "f"(x1.x * v1), "f"(x1.y * v1), "f"(x1.z * v1), "f"(x1.w * v1));
        asm volatile("red.global.add.v4.f32 [%0], {%1,%2,%3,%4};"
                     :: "l"(p2), "f"(x2.x * v2), "f"(x2.y * v2), "f"(x2.z * v2), "f"(x2.w * v2));
        asm volatile("red.global.add.v4.f32 [%0], {%1,%2,%3,%4};"
                     :: "l"(p3), "f"(x3.x * v3), "f"(x3.y * v3), "f"(x3.z * v3), "f"(x3.w * v3));
    }
}

// ---------------- prediction ----------------
__global__ __launch_bounds__(256) void k_pred(const int* __restrict__ ui,
                                              const int* __restrict__ ii,
                                              float* __restrict__ out, int out_size) {
    __shared__ int su[512];
    __shared__ int sI[512];
    int base = blockIdx.x << 9;
    int t = threadIdx.x;
    int n = NPAIRS - base; if (n > 512) n = 512;
    for (int i = t; i < n; i += 256) { su[i] = ui[base + i]; sI[i] = ii[base + i]; }
    __syncthreads();

    int sub = t & 7, grp = t >> 3;
    if (n == 512) {
#pragma unroll
        for (int pass = 0; pass < 8; ++pass) {
            int p = grp + pass * 64;
            int u0 = su[p],      i0 = sI[p];
            int u1 = su[p + 32], i1 = sI[p + 32];
            float4 a0 = *reinterpret_cast<const float4*>(&g_last[(size_t)u0 * DIM + sub * 4]);
            float4 b0 = *reinterpret_cast<const float4*>(&g_item_fus[(size_t)i0 * DIM + sub * 4]);
            float4 a1 = *reinterpret_cast<const float4*>(&g_last[(size_t)u1 * DIM + sub * 4]);
            float4 b1 = *reinterpret_cast<const float4*>(&g_item_fus[(size_t)i1 * DIM + sub * 4]);
            float d0 = a0.x * b0.x + a0.y * b0.y + a0.z * b0.z + a0.w * b0.w;
            float d1 = a1.x * b1.x + a1.y * b1.y + a1.z * b1.z + a1.w * b1.w;
#pragma unroll
            for (int o = 4; o; o >>= 1) {
                d0 += __shfl_down_sync(0xffffffffu, d0, o, 8);
                d1 += __shfl_down_sync(0xffffffffu, d1, o, 8);
            }
            if (sub == 0) {
                int gp0 = base + p, gp1 = base + p + 32;
                out[gp0] = d0;
                out[NPAIRS + gp0] = 1.f / (1.f + expf(-d0));
                out[gp1] = d1;
                out[NPAIRS + gp1] = 1.f / (1.f + expf(-d1));
            }
        }
    } else {
        for (int p = grp; p < n; p += 32) {
            int u  = su[p];
            int it = sI[p];
            float4 a = *reinterpret_cast<const float4*>(&g_last[(size_t)u * DIM + sub * 4]);
            float4 b = *reinterpret_cast<const float4*>(&g_item_fus[(size_t)it * DIM + sub * 4]);
            float d = a.x * b.x + a.y * b.y + a.z * b.z + a.w * b.w;
#pragma unroll
            for (int o = 4; o; o >>= 1) d += __shfl_down_sync(0xffffffffu, d, o, 8);
            if (sub == 0) {
                int gp = base + p;
                if (gp < out_size) out[gp] = d;
                if (NPAIRS + gp < out_size) out[NPAIRS + gp] = 1.f / (1.f + expf(-d));
            }
        }
    }
}

// ---------------- launch: fork/join across two side streams ----------------
extern "C" void kernel_launch(void* const* d_in, const int* in_sizes, int n_in,
                              void* d_out, int out_size) {
    const float* uf    = (const float*)d_in[0];
    const float* itf   = (const float*)d_in[1];
    const float* uemb  = (const float*)d_in[2];
    const float* iemb  = (const float*)d_in[3];
    const float* wr_w  = (const float*)d_in[4];
    const float* wr_b  = (const float*)d_in[5];
    const int*   srows = (const int*)d_in[6];
    const int*   scols = (const int*)d_in[7];
    const float* svals = (const float*)d_in[8];
    const int*   urows = (const int*)d_in[9];
    const int*   ucols = (const int*)d_in[10];
    const float* uvals = (const float*)d_in[11];
    const int*   uidx  = (const int*)d_in[12];
    const int*   iidx  = (const int*)d_in[13];
    float* out = (float*)d_out;

    static cudaStream_t sA = 0, sB = 0;
    static cudaEvent_t  eFork = 0, eA = 0, eB = 0;
    if (sA == 0) {
        cudaStreamCreateWithFlags(&sA, cudaStreamNonBlocking);
        cudaStreamCreateWithFlags(&sB, cudaStreamNonBlocking);
        cudaEventCreateWithFlags(&eFork, cudaEventDisableTiming);
        cudaEventCreateWithFlags(&eA, cudaEventDisableTiming);
        cudaEventCreateWithFlags(&eB, cudaEventDisableTiming);
    }

    k_init<<<(NUSERS * DIM / 4 + 255) / 256, 256>>>();
    k_colsum<<<1, 256>>>(wr_w);
    cudaEventRecord(eFork, 0);
    cudaStreamWaitEvent(sA, eFork, 0);
    cudaStreamWaitEvent(sB, eFork, 0);

    // stream A: item chain -> UI SpMM
    k_gemm<<<(NITEMS + 63) / 64, 128, 0, sA>>>(itf, wr_w, NITEMS, 2, 1);
    k_scal<<<1, 1, 0, sA>>>(2, (double)NITEMS * NFEATS, 0);
    k_epi<<<(NITEMS * DIM + 255) / 256, 256, 0, sA>>>(wr_b, NITEMS * DIM, 2, 6, 1);
    k_scal<<<1, 1, 0, sA>>>(6, (double)(NITEMS * DIM), 1);
    k_fusion<<<(NITEMS * DIM + 255) / 256, 256, 0, sA>>>(iemb, NITEMS * DIM, 6, 1);
    k_spmm<<<EUI / SPMM_EB, 256, 0, sA>>>(urows, ucols, uvals, 0, 0);

    // stream B: user chain -> soc1 -> soc2
    k_gemm<<<(NUSERS + 63) / 64, 128, 0, sB>>>(uf, wr_w, NUSERS, 0, 0);
    k_scal<<<1, 1, 0, sB>>>(0, (double)NUSERS * NFEATS, 0);
    k_epi<<<(NUSERS * DIM + 255) / 256, 256, 0, sB>>>(wr_b, NUSERS * DIM, 0, 4, 0);
    k_scal<<<1, 1, 0, sB>>>(4, (double)(NUSERS * DIM), 1);
    k_fusion<<<(NUSERS * DIM + 255) / 256, 256, 0, sB>>>(uemb, NUSERS * DIM, 4, 0);
    k_spmm<<<ESOC / SPMM_EB, 256, 0, sB>>>(srows, scols, svals, 1, 1);
    k_spmm<<<ESOC / SPMM_EB, 256, 0, sB>>>(srows, scols, svals, 2, 0);

    // join
    cudaEventRecord(eA, sA);
    cudaEventRecord(eB, sB);
    cudaStreamWaitEvent(0, eA, 0);
    cudaStreamWaitEvent(0, eB, 0);
    k_pred<<<(NPAIRS + 511) / 512, 256>>>(uidx, iidx, out, out_size);
}